// round 4
// baseline (speedup 1.0000x reference)
#include <cuda_runtime.h>

#define T_STEPS 301
#define IN_DIM  40
#define H_DIM   64
#define G_DIM   256      // 4*H
#define BTILE   32       // samples per CTA
#define NTHR    256
#define XST     36       // floats per operand row (32 samples + pad, 16B-aligned)

// Shared memory layout (floats)
#define WZ_OFF   0
#define WZ_SIZE  (104 * G_DIM)            // 26624 : W[k][g]; k<40 -> w_ih, else w_hh
#define XB0_OFF  (WZ_OFF + WZ_SIZE)       // x double buffers [40][XST]
#define XB1_OFF  (XB0_OFF + IN_DIM * XST)
#define HB_OFF   (XB1_OFF + IN_DIM * XST) // h buffer [64][XST]
#define BIAS_OFF (HB_OFF + H_DIM * XST)
#define CLF_OFF  (BIAS_OFF + G_DIM)
#define SMEM_FLOATS (CLF_OFF + BTILE * 65)   // 34144 floats = 136576 B

typedef unsigned long long ull;

__device__ __forceinline__ ull pack2(float a, float b) {
    ull r; asm("mov.b64 %0, {%1,%2};" : "=l"(r) : "f"(a), "f"(b)); return r;
}
__device__ __forceinline__ void unpack2(ull v, float& a, float& b) {
    asm("mov.b64 {%0,%1}, %2;" : "=f"(a), "=f"(b) : "l"(v));
}
__device__ __forceinline__ void ffma2(ull& d, ull a, ull b) {
    asm("fma.rn.f32x2 %0, %1, %2, %0;" : "+l"(d) : "l"(a), "l"(b));
}
__device__ __forceinline__ float tanha(float x) {
    float y; asm("tanh.approx.f32 %0, %1;" : "=f"(y) : "f"(x)); return y;
}
__device__ __forceinline__ float sigm(float x) {
    return fmaf(0.5f, tanha(0.5f * x), 0.5f);
}

// one k-slice: 4 weight splats x 4 sample-pairs
__device__ __forceinline__ void gemm_k(const float* __restrict__ wr,
                                       const float* __restrict__ xrow,
                                       ull acc[4][4])
{
    float w0 = wr[0], w1 = wr[64], w2 = wr[128], w3 = wr[192];
    ull W0 = pack2(w0, w0), W1 = pack2(w1, w1);
    ull W2 = pack2(w2, w2), W3 = pack2(w3, w3);
    ulonglong2 xlo = *(const ulonglong2*)(xrow);
    ulonglong2 xhi = *(const ulonglong2*)(xrow + 4);
    ffma2(acc[0][0], W0, xlo.x); ffma2(acc[0][1], W0, xlo.y);
    ffma2(acc[0][2], W0, xhi.x); ffma2(acc[0][3], W0, xhi.y);
    ffma2(acc[1][0], W1, xlo.x); ffma2(acc[1][1], W1, xlo.y);
    ffma2(acc[1][2], W1, xhi.x); ffma2(acc[1][3], W1, xhi.y);
    ffma2(acc[2][0], W2, xlo.x); ffma2(acc[2][1], W2, xlo.y);
    ffma2(acc[2][2], W2, xhi.x); ffma2(acc[2][3], W2, xhi.y);
    ffma2(acc[3][0], W3, xlo.x); ffma2(acc[3][1], W3, xlo.y);
    ffma2(acc[3][2], W3, xhi.x); ffma2(acc[3][3], W3, xhi.y);
}

__global__ void __launch_bounds__(NTHR, 1)
lstm_fused_kernel(const float* __restrict__ x,
                  const float* __restrict__ w_ih,
                  const float* __restrict__ w_hh,
                  const float* __restrict__ b_ih,
                  const float* __restrict__ b_hh,
                  const float* __restrict__ w_clf,
                  const float* __restrict__ b_clf,
                  float* __restrict__ out)
{
    extern __shared__ float sm[];
    float* Wz    = sm + WZ_OFF;
    float* xb[2] = { sm + XB0_OFF, sm + XB1_OFF };
    float* hb    = sm + HB_OFF;
    float* bias  = sm + BIAS_OFF;
    float* shclf = sm + CLF_OFF;

    const int tid  = threadIdx.x;
    const int j    = tid & 63;     // gate column within H
    const int bt   = tid >> 6;     // sample octet 0..3
    const int base = blockIdx.x * BTILE;
    const int boff = 8 * bt;

    // ---- stage weights transposed into [k][g] ----
    for (int idx = tid; idx < WZ_SIZE; idx += NTHR) {
        int g = idx & 255, k = idx >> 8;
        Wz[idx] = (k < IN_DIM) ? w_ih[g * IN_DIM + k]
                               : w_hh[g * H_DIM + (k - IN_DIM)];
    }
    bias[tid] = b_ih[tid] + b_hh[tid];
    for (int f = tid; f < H_DIM * BTILE; f += NTHR)
        hb[(f >> 5) * XST + (f & 31)] = 0.f;

    // ---- x staging: xr regs hold one timestep (5 floats/thread) ----
    float xr[5];
    int xf_b[5], xf_k[5];
    #pragma unroll
    for (int i = 0; i < 5; i++) {
        int f = tid + i * NTHR;
        xf_b[i] = f / IN_DIM;
        xf_k[i] = f - xf_b[i] * IN_DIM;
    }
    const float* xbase = x + (size_t)base * (T_STEPS * IN_DIM);

    #pragma unroll
    for (int i = 0; i < 5; i++)
        xr[i] = xbase[(size_t)xf_b[i] * (T_STEPS * IN_DIM) + xf_k[i]];       // x_0
    #pragma unroll
    for (int i = 0; i < 5; i++)
        xb[0][xf_k[i] * XST + xf_b[i]] = xr[i];
    #pragma unroll
    for (int i = 0; i < 5; i++)
        xr[i] = xbase[(size_t)xf_b[i] * (T_STEPS * IN_DIM) + IN_DIM + xf_k[i]]; // x_1

    __syncthreads();  // W, bias, hb, xb[0] visible

    // packed biases in registers
    ull bp[4];
    #pragma unroll
    for (int g = 0; g < 4; g++) { float bg = bias[j + 64 * g]; bp[g] = pack2(bg, bg); }

    // accZ = bias + x-part(x_0)
    ull accZ[4][4];
    #pragma unroll
    for (int g = 0; g < 4; g++)
        #pragma unroll
        for (int p = 0; p < 4; p++) accZ[g][p] = bp[g];
    #pragma unroll 8
    for (int k = 0; k < IN_DIM; k++)
        gemm_k(Wz + k * G_DIM + j, xb[0] + k * XST + boff, accZ);

    #pragma unroll
    for (int i = 0; i < 5; i++)
        xb[1][xf_k[i] * XST + xf_b[i]] = xr[i];                               // stage x_1
    #pragma unroll
    for (int i = 0; i < 5; i++)
        xr[i] = xbase[(size_t)xf_b[i] * (T_STEPS * IN_DIM) + 2 * IN_DIM + xf_k[i]]; // x_2

    __syncthreads();  // xb[1] visible

    float c[8], clf[8];
    #pragma unroll
    for (int i = 0; i < 8; i++) { c[i] = 0.f; clf[i] = 0.f; }

    int cur = 1;

    for (int t = 0; t < T_STEPS - 1; t++) {
        // ---- h-part: accZ += W_hh * h_{t-1} ----
        #pragma unroll 8
        for (int k = 0; k < H_DIM; k++)
            gemm_k(Wz + (IN_DIM + k) * G_DIM + j, hb + k * XST + boff, accZ);

        // ---- gates (MUFU) + x-part for t+1 (FMA) : independent, interleavable ----
        float wc = __ldg(&w_clf[t * H_DIM + j]);
        float hv[8];
        #pragma unroll
        for (int p = 0; p < 4; p++) {
            float zi0, zi1, zf0, zf1, zg0, zg1, zo0, zo1;
            unpack2(accZ[0][p], zi0, zi1);
            unpack2(accZ[1][p], zf0, zf1);
            unpack2(accZ[2][p], zg0, zg1);
            unpack2(accZ[3][p], zo0, zo1);
            float cc0 = sigm(zf0) * c[2*p]   + sigm(zi0) * tanha(zg0);
            float cc1 = sigm(zf1) * c[2*p+1] + sigm(zi1) * tanha(zg1);
            c[2*p]   = cc0;  c[2*p+1] = cc1;
            hv[2*p]   = sigm(zo0) * tanha(cc0);
            hv[2*p+1] = sigm(zo1) * tanha(cc1);
            clf[2*p]   = fmaf(hv[2*p],   wc, clf[2*p]);
            clf[2*p+1] = fmaf(hv[2*p+1], wc, clf[2*p+1]);
        }

        ull accX[4][4];
        #pragma unroll
        for (int g = 0; g < 4; g++)
            #pragma unroll
            for (int p = 0; p < 4; p++) accX[g][p] = bp[g];
        {
            const float* xc = xb[cur];
            #pragma unroll 8
            for (int k = 0; k < IN_DIM; k++)
                gemm_k(Wz + k * G_DIM + j, xc + k * XST + boff, accX);
        }

        __syncthreads();  // everyone done reading hb (h_{t-1}) and xb[cur]

        // store h_t (2x STS.128) and stage x_{t+2}
        *(float4*)(hb + j * XST + boff)     = make_float4(hv[0], hv[1], hv[2], hv[3]);
        *(float4*)(hb + j * XST + boff + 4) = make_float4(hv[4], hv[5], hv[6], hv[7]);
        {
            float* xn = xb[cur ^ 1];
            #pragma unroll
            for (int i = 0; i < 5; i++)
                xn[xf_k[i] * XST + xf_b[i]] = xr[i];
        }
        if (t <= T_STEPS - 4) {
            #pragma unroll
            for (int i = 0; i < 5; i++)
                xr[i] = xbase[(size_t)xf_b[i] * (T_STEPS * IN_DIM) + (t + 3) * IN_DIM + xf_k[i]];
        }

        __syncthreads();  // h_t and x_{t+2} visible

        #pragma unroll
        for (int g = 0; g < 4; g++)
            #pragma unroll
            for (int p = 0; p < 4; p++) accZ[g][p] = accX[g][p];
        cur ^= 1;
    }

    // ---- epilogue: t = T-1 (no next x-part, no h store) ----
    {
        #pragma unroll 8
        for (int k = 0; k < H_DIM; k++)
            gemm_k(Wz + (IN_DIM + k) * G_DIM + j, hb + k * XST + boff, accZ);
        float wc = __ldg(&w_clf[(T_STEPS - 1) * H_DIM + j]);
        #pragma unroll
        for (int p = 0; p < 4; p++) {
            float zi0, zi1, zf0, zf1, zg0, zg1, zo0, zo1;
            unpack2(accZ[0][p], zi0, zi1);
            unpack2(accZ[1][p], zf0, zf1);
            unpack2(accZ[2][p], zg0, zg1);
            unpack2(accZ[3][p], zo0, zo1);
            float cc0 = sigm(zf0) * c[2*p]   + sigm(zi0) * tanha(zg0);
            float cc1 = sigm(zf1) * c[2*p+1] + sigm(zi1) * tanha(zg1);
            float h0 = sigm(zo0) * tanha(cc0);
            float h1 = sigm(zo1) * tanha(cc1);
            clf[2*p]   = fmaf(h0, wc, clf[2*p]);
            clf[2*p+1] = fmaf(h1, wc, clf[2*p+1]);
        }
    }

    // ---- classifier reduction over j ----
    __syncthreads();
    #pragma unroll
    for (int p = 0; p < 4; p++) {
        shclf[(boff + 2*p)     * 65 + j] = clf[2*p];
        shclf[(boff + 2*p + 1) * 65 + j] = clf[2*p + 1];
    }
    __syncthreads();
    if (tid < BTILE) {
        float s = b_clf[0];
        #pragma unroll 8
        for (int jj = 0; jj < H_DIM; jj++) s += shclf[tid * 65 + jj];
        out[base + tid] = s;
    }
}

extern "C" void kernel_launch(void* const* d_in, const int* in_sizes, int n_in,
                              void* d_out, int out_size)
{
    const float* x     = (const float*)d_in[0];
    const float* w_ih  = (const float*)d_in[1];
    const float* w_hh  = (const float*)d_in[2];
    const float* b_ih  = (const float*)d_in[3];
    const float* b_hh  = (const float*)d_in[4];
    const float* w_clf = (const float*)d_in[5];
    const float* b_clf = (const float*)d_in[6];
    float* out = (float*)d_out;

    const int B = in_sizes[0] / (T_STEPS * IN_DIM);   // 4096
    const int smem_bytes = SMEM_FLOATS * sizeof(float);

    cudaFuncSetAttribute(lstm_fused_kernel,
                         cudaFuncAttributeMaxDynamicSharedMemorySize, smem_bytes);
    lstm_fused_kernel<<<B / BTILE, NTHR, smem_bytes>>>(
        x, w_ih, w_hh, b_ih, b_hh, w_clf, b_clf, out);
}

// round 5
// speedup vs baseline: 1.0489x; 1.0489x over previous
#include <cuda_runtime.h>

#define T_STEPS 301
#define IN_DIM  40
#define H_DIM   64
#define G_DIM   256      // 4*H
#define KTOT    104      // IN + H
#define BTILE   32       // samples per CTA
#define NTHR    512      // 16 warps = 4 per SMSP
#define XST     36       // floats per operand row (32 samples + pad)
#define TIN     (T_STEPS * IN_DIM)

// Shared memory layout (floats)
#define WZ_OFF   0
#define WZ_SIZE  (KTOT * G_DIM)          // 26624 : Wz[k][j*4+g]  (4 gates packed per column)
#define XH_OFF   (WZ_OFF + WZ_SIZE)
#define XH_SIZE  (KTOT * XST)            // rows k<40: x_t, rows >=40: h_{t-1}
#define BIAS_OFF (XH_OFF + XH_SIZE)
#define CLF_OFF  (BIAS_OFF + G_DIM)
#define SMEM_FLOATS (CLF_OFF + BTILE * 65)   // 32704 floats = 130816 B

typedef unsigned long long ull;

__device__ __forceinline__ ull pack2(float a, float b) {
    ull r; asm("mov.b64 %0, {%1,%2};" : "=l"(r) : "f"(a), "f"(b)); return r;
}
__device__ __forceinline__ void unpack2(ull v, float& a, float& b) {
    asm("mov.b64 {%0,%1}, %2;" : "=f"(a), "=f"(b) : "l"(v));
}
__device__ __forceinline__ void ffma2(ull& d, ull a, ull b) {
    asm("fma.rn.f32x2 %0, %1, %2, %0;" : "+l"(d) : "l"(a), "l"(b));
}
__device__ __forceinline__ float tanha(float x) {
    float y; asm("tanh.approx.f32 %0, %1;" : "=f"(y) : "f"(x)); return y;
}
__device__ __forceinline__ float sigm(float x) {
    return fmaf(0.5f, tanha(0.5f * x), 0.5f);
}

__global__ void __launch_bounds__(NTHR, 1)
lstm_fused_kernel(const float* __restrict__ x,
                  const float* __restrict__ w_ih,
                  const float* __restrict__ w_hh,
                  const float* __restrict__ b_ih,
                  const float* __restrict__ b_hh,
                  const float* __restrict__ w_clf,
                  const float* __restrict__ b_clf,
                  float* __restrict__ out)
{
    extern __shared__ float sm[];
    float* Wz    = sm + WZ_OFF;
    float* xhf   = sm + XH_OFF;
    float* bias  = sm + BIAS_OFF;
    float* shclf = sm + CLF_OFF;

    const int tid  = threadIdx.x;
    const int j    = tid & 63;     // gate column within H
    const int bt   = tid >> 6;     // sample quartet 0..7
    const int boff = 4 * bt;       // first sample of this thread
    const int base = blockIdx.x * BTILE;

    // ---- stage weights: Wz[k][j*4+g] so one LDS.128 yields all 4 gate weights ----
    for (int idx = tid; idx < WZ_SIZE; idx += NTHR) {
        int k = idx >> 8, r = idx & 255;
        int jj = r >> 2, g = r & 3;
        Wz[idx] = (k < IN_DIM) ? w_ih[(g * H_DIM + jj) * IN_DIM + k]
                               : w_hh[(g * H_DIM + jj) * H_DIM + (k - IN_DIM)];
    }
    if (tid < G_DIM) bias[tid] = b_ih[tid] + b_hh[tid];
    // zero h rows
    for (int f = tid; f < H_DIM * BTILE; f += NTHR)
        xhf[(IN_DIM + (f >> 5)) * XST + (f & 31)] = 0.f;

    // ---- x staging indices: 1280 floats / 512 threads -> up to 3 each ----
    int xf_b[3], xf_k[3], xf_v[3];
    #pragma unroll
    for (int i = 0; i < 3; i++) {
        int f = tid + i * NTHR;
        xf_v[i] = (f < BTILE * IN_DIM);
        int ff = xf_v[i] ? f : 0;
        xf_b[i] = ff / IN_DIM;
        xf_k[i] = ff - xf_b[i] * IN_DIM;
    }
    const float* xbase = x + (size_t)base * TIN;

    float xr[3];
    #pragma unroll
    for (int i = 0; i < 3; i++)
        if (xf_v[i]) xr[i] = xbase[(size_t)xf_b[i] * TIN + xf_k[i]];   // x_0

    __syncthreads();   // weights + bias + h-zero visible

    // packed biases in registers
    ull bp[4];
    #pragma unroll
    for (int g = 0; g < 4; g++) { float bg = bias[g * H_DIM + j]; bp[g] = pack2(bg, bg); }

    float c[4], clf[4];
    #pragma unroll
    for (int i = 0; i < 4; i++) { c[i] = 0.f; clf[i] = 0.f; }

    for (int t = 0; t < T_STEPS; t++) {
        // stage x_t (x region only; h region owned by gate stores of t-1, already synced)
        #pragma unroll
        for (int i = 0; i < 3; i++)
            if (xf_v[i]) xhf[xf_k[i] * XST + xf_b[i]] = xr[i];
        // prefetch x_{t+1}
        if (t + 1 < T_STEPS) {
            #pragma unroll
            for (int i = 0; i < 3; i++)
                if (xf_v[i]) xr[i] = xbase[(size_t)xf_b[i] * TIN + (t + 1) * IN_DIM + xf_k[i]];
        }
        float wc = __ldg(&w_clf[t * H_DIM + j]);

        __syncthreads();   // x_t staged + h_{t-1} staged

        // ---- z = [x_t ; h_{t-1}] @ W^T : 104-deep, 8 f32x2 accumulators ----
        ull acc[4][2];
        #pragma unroll
        for (int g = 0; g < 4; g++) { acc[g][0] = bp[g]; acc[g][1] = bp[g]; }

        const float* wp = Wz + 4 * j;
        const float* xp = xhf + boff;
        #pragma unroll 8
        for (int k = 0; k < KTOT; k++) {
            float4 wv = *(const float4*)(wp + k * G_DIM);        // 4 gate weights
            ulonglong2 xv = *(const ulonglong2*)(xp + k * XST);  // 4 samples (broadcast)
            ull W0 = pack2(wv.x, wv.x), W1 = pack2(wv.y, wv.y);
            ull W2 = pack2(wv.z, wv.z), W3 = pack2(wv.w, wv.w);
            ffma2(acc[0][0], W0, xv.x); ffma2(acc[0][1], W0, xv.y);
            ffma2(acc[1][0], W1, xv.x); ffma2(acc[1][1], W1, xv.y);
            ffma2(acc[2][0], W2, xv.x); ffma2(acc[2][1], W2, xv.y);
            ffma2(acc[3][0], W3, xv.x); ffma2(acc[3][1], W3, xv.y);
        }

        __syncthreads();   // all GEMM reads done before h rows are overwritten

        // ---- gates ----
        float hv[4];
        #pragma unroll
        for (int p = 0; p < 2; p++) {
            float zi0, zi1, zf0, zf1, zg0, zg1, zo0, zo1;
            unpack2(acc[0][p], zi0, zi1);
            unpack2(acc[1][p], zf0, zf1);
            unpack2(acc[2][p], zg0, zg1);
            unpack2(acc[3][p], zo0, zo1);
            float cc0 = sigm(zf0) * c[2*p]   + sigm(zi0) * tanha(zg0);
            float cc1 = sigm(zf1) * c[2*p+1] + sigm(zi1) * tanha(zg1);
            c[2*p]   = cc0;  c[2*p+1] = cc1;
            hv[2*p]   = sigm(zo0) * tanha(cc0);
            hv[2*p+1] = sigm(zo1) * tanha(cc1);
            clf[2*p]   = fmaf(hv[2*p],   wc, clf[2*p]);
            clf[2*p+1] = fmaf(hv[2*p+1], wc, clf[2*p+1]);
        }
        // store h_t (one STS.128); h region reads resume only after next sync
        *(float4*)(xhf + (IN_DIM + j) * XST + boff) =
            make_float4(hv[0], hv[1], hv[2], hv[3]);
    }

    // ---- classifier reduction over j ----
    __syncthreads();
    #pragma unroll
    for (int p = 0; p < 4; p++)
        shclf[(boff + p) * 65 + j] = clf[p];
    __syncthreads();
    if (tid < BTILE) {
        float s = b_clf[0];
        #pragma unroll 8
        for (int jj = 0; jj < H_DIM; jj++) s += shclf[tid * 65 + jj];
        out[base + tid] = s;
    }
}

extern "C" void kernel_launch(void* const* d_in, const int* in_sizes, int n_in,
                              void* d_out, int out_size)
{
    const float* x     = (const float*)d_in[0];
    const float* w_ih  = (const float*)d_in[1];
    const float* w_hh  = (const float*)d_in[2];
    const float* b_ih  = (const float*)d_in[3];
    const float* b_hh  = (const float*)d_in[4];
    const float* w_clf = (const float*)d_in[5];
    const float* b_clf = (const float*)d_in[6];
    float* out = (float*)d_out;

    const int B = in_sizes[0] / TIN;   // 4096
    const int smem_bytes = SMEM_FLOATS * sizeof(float);

    cudaFuncSetAttribute(lstm_fused_kernel,
                         cudaFuncAttributeMaxDynamicSharedMemorySize, smem_bytes);
    lstm_fused_kernel<<<B / BTILE, NTHR, smem_bytes>>>(
        x, w_ih, w_hh, b_ih, b_hh, w_clf, b_clf, out);
}

// round 6
// speedup vs baseline: 1.0684x; 1.0186x over previous
#include <cuda_runtime.h>

#define T_STEPS 301
#define IN_DIM  40
#define H_DIM   64
#define G_DIM   256      // 4*H
#define KTOT    104      // IN + H
#define KHALF   52
#define BTILE   32       // samples per CTA
#define NTHR    512      // 16 warps = 4 per SMSP
#define XST     36       // floats per operand row (32 samples + pad)
#define TIN     (T_STEPS * IN_DIM)

// Shared memory layout (floats)
#define WZ_OFF   0
#define WZ_SIZE  (KTOT * G_DIM)          // 26624 : Wz[k][4*j+g] (4 gates packed)
#define XH_OFF   (WZ_OFF + WZ_SIZE)
#define XH_SIZE  (KTOT * XST)            // rows k<40: x_t, rows >=40: h_{t-1}
#define BIAS_OFF (XH_OFF + XH_SIZE)
#define CLF_OFF  (BIAS_OFF + G_DIM)
#define SMEM_FLOATS (CLF_OFF + BTILE * 65)   // 32704 floats = 130816 B

typedef unsigned long long ull;
typedef unsigned int uint;

__device__ __forceinline__ ull pack2(float a, float b) {
    ull r; asm("mov.b64 %0, {%1,%2};" : "=l"(r) : "f"(a), "f"(b)); return r;
}
__device__ __forceinline__ void unpack2(ull v, float& a, float& b) {
    asm("mov.b64 {%0,%1}, %2;" : "=f"(a), "=f"(b) : "l"(v));
}
__device__ __forceinline__ void ffma2(ull& d, ull a, ull b) {
    asm("fma.rn.f32x2 %0, %1, %2, %0;" : "+l"(d) : "l"(a), "l"(b));
}
__device__ __forceinline__ ull addf2(ull a, ull b) {
    ull r; asm("add.rn.f32x2 %0, %1, %2;" : "=l"(r) : "l"(a), "l"(b)); return r;
}
__device__ __forceinline__ ull shfl_xor16_64(ull v) {
    uint lo, hi;
    asm("mov.b64 {%0,%1}, %2;" : "=r"(lo), "=r"(hi) : "l"(v));
    lo = __shfl_xor_sync(0xFFFFFFFFu, lo, 16);
    hi = __shfl_xor_sync(0xFFFFFFFFu, hi, 16);
    ull r; asm("mov.b64 %0, {%1,%2};" : "=l"(r) : "r"(lo), "r"(hi));
    return r;
}
__device__ __forceinline__ float tanha(float x) {
    float y; asm("tanh.approx.f32 %0, %1;" : "=f"(y) : "f"(x)); return y;
}
__device__ __forceinline__ float sigm(float x) {
    return fmaf(0.5f, tanha(0.5f * x), 0.5f);
}

__global__ void __launch_bounds__(NTHR, 1)
lstm_fused_kernel(const float* __restrict__ x,
                  const float* __restrict__ w_ih,
                  const float* __restrict__ w_hh,
                  const float* __restrict__ b_ih,
                  const float* __restrict__ b_hh,
                  const float* __restrict__ w_clf,
                  const float* __restrict__ b_clf,
                  float* __restrict__ out)
{
    extern __shared__ float sm[];
    float* Wz    = sm + WZ_OFF;
    float* xhf   = sm + XH_OFF;
    float* bias  = sm + BIAS_OFF;
    float* shclf = sm + CLF_OFF;

    const int tid  = threadIdx.x;
    const int lane = tid & 31;
    const int w    = tid >> 5;          // warp 0..15
    const int jl   = lane & 15;
    const int kt   = lane >> 4;         // k-half: 0 or 1
    const int j    = jl + 16 * (w & 3); // gate column 0..63
    const int bt   = w >> 2;            // sample octet 0..3
    const int boff = 8 * bt;
    const int k0   = KHALF * kt;        // this thread's k offset
    const int base = blockIdx.x * BTILE;

    // ---- stage weights: Wz[k][4*j+g] so one LDS.128 yields all 4 gate weights ----
    for (int idx = tid; idx < WZ_SIZE; idx += NTHR) {
        int k = idx >> 8, r = idx & 255;
        int jj = r >> 2, g = r & 3;
        Wz[idx] = (k < IN_DIM) ? w_ih[(g * H_DIM + jj) * IN_DIM + k]
                               : w_hh[(g * H_DIM + jj) * H_DIM + (k - IN_DIM)];
    }
    if (tid < G_DIM) bias[tid] = b_ih[tid] + b_hh[tid];
    // zero h rows
    for (int f = tid; f < H_DIM * BTILE; f += NTHR)
        xhf[(IN_DIM + (f >> 5)) * XST + (f & 31)] = 0.f;

    // ---- x staging indices: 1280 floats / 512 threads -> up to 3 each ----
    int xf_b[3], xf_k[3], xf_v[3];
    #pragma unroll
    for (int i = 0; i < 3; i++) {
        int f = tid + i * NTHR;
        xf_v[i] = (f < BTILE * IN_DIM);
        int ff = xf_v[i] ? f : 0;
        xf_b[i] = ff / IN_DIM;
        xf_k[i] = ff - xf_b[i] * IN_DIM;
    }
    const float* xbase = x + (size_t)base * TIN;

    float xr[3];
    #pragma unroll
    for (int i = 0; i < 3; i++)
        if (xf_v[i]) xr[i] = xbase[(size_t)xf_b[i] * TIN + xf_k[i]];   // x_0

    __syncthreads();   // weights + bias + h-zero visible

    // packed biases (only kt==0 seeds them into the accumulators)
    ull bp[4];
    #pragma unroll
    for (int g = 0; g < 4; g++) {
        float bg = (kt == 0) ? bias[g * H_DIM + j] : 0.f;
        bp[g] = pack2(bg, bg);
    }

    float c[4], clf[4];
    #pragma unroll
    for (int i = 0; i < 4; i++) { c[i] = 0.f; clf[i] = 0.f; }

    const float* wp0 = Wz + (size_t)k0 * G_DIM + 4 * j;
    const float* xp0 = xhf + (size_t)k0 * XST + boff;

    for (int t = 0; t < T_STEPS; t++) {
        // stage x_t
        #pragma unroll
        for (int i = 0; i < 3; i++)
            if (xf_v[i]) xhf[xf_k[i] * XST + xf_b[i]] = xr[i];
        // prefetch x_{t+1}
        if (t + 1 < T_STEPS) {
            #pragma unroll
            for (int i = 0; i < 3; i++)
                if (xf_v[i]) xr[i] = xbase[(size_t)xf_b[i] * TIN + (t + 1) * IN_DIM + xf_k[i]];
        }
        float wc = __ldg(&w_clf[t * H_DIM + j]);

        __syncthreads();   // x_t + h_{t-1} staged

        // ---- partial z over this thread's K half : 16 f32x2 accumulators ----
        ull acc[4][4];     // [gate][sample-pair]
        #pragma unroll
        for (int g = 0; g < 4; g++)
            #pragma unroll
            for (int p = 0; p < 4; p++) acc[g][p] = bp[g];

        #pragma unroll 4
        for (int k = 0; k < KHALF; k++) {
            float4 wv = *(const float4*)(wp0 + k * G_DIM);
            ulonglong2 xlo = *(const ulonglong2*)(xp0 + k * XST);      // samples 0..3 of octet
            ulonglong2 xhi = *(const ulonglong2*)(xp0 + k * XST + 4);  // samples 4..7
            ull W0 = pack2(wv.x, wv.x), W1 = pack2(wv.y, wv.y);
            ull W2 = pack2(wv.z, wv.z), W3 = pack2(wv.w, wv.w);
            ffma2(acc[0][0], W0, xlo.x); ffma2(acc[0][1], W0, xlo.y);
            ffma2(acc[0][2], W0, xhi.x); ffma2(acc[0][3], W0, xhi.y);
            ffma2(acc[1][0], W1, xlo.x); ffma2(acc[1][1], W1, xlo.y);
            ffma2(acc[1][2], W1, xhi.x); ffma2(acc[1][3], W1, xhi.y);
            ffma2(acc[2][0], W2, xlo.x); ffma2(acc[2][1], W2, xlo.y);
            ffma2(acc[2][2], W2, xhi.x); ffma2(acc[2][3], W2, xhi.y);
            ffma2(acc[3][0], W3, xlo.x); ffma2(acc[3][1], W3, xlo.y);
            ffma2(acc[3][2], W3, xhi.x); ffma2(acc[3][3], W3, xhi.y);
        }

        // ---- butterfly across kt halves: both lanes end with full z ----
        #pragma unroll
        for (int g = 0; g < 4; g++) {
            #pragma unroll
            for (int p = 0; p < 4; p++)
                acc[g][p] = addf2(acc[g][p], shfl_xor16_64(acc[g][p]));
        }

        __syncthreads();   // all GEMM reads of xhf done before h rows are overwritten

        // ---- gates: kt=0 handles pairs 0,1 (samples 0-3); kt=1 pairs 2,3 ----
        float hv[4];
        #pragma unroll
        for (int lp = 0; lp < 2; lp++) {
            int p = 2 * kt + lp;
            float zi0, zi1, zf0, zf1, zg0, zg1, zo0, zo1;
            unpack2(acc[0][p], zi0, zi1);
            unpack2(acc[1][p], zf0, zf1);
            unpack2(acc[2][p], zg0, zg1);
            unpack2(acc[3][p], zo0, zo1);
            float cc0 = sigm(zf0) * c[2*lp]   + sigm(zi0) * tanha(zg0);
            float cc1 = sigm(zf1) * c[2*lp+1] + sigm(zi1) * tanha(zg1);
            c[2*lp]   = cc0;  c[2*lp+1] = cc1;
            hv[2*lp]   = sigm(zo0) * tanha(cc0);
            hv[2*lp+1] = sigm(zo1) * tanha(cc1);
            clf[2*lp]   = fmaf(hv[2*lp],   wc, clf[2*lp]);
            clf[2*lp+1] = fmaf(hv[2*lp+1], wc, clf[2*lp+1]);
        }
        // store h_t for this thread's 4 samples (one STS.128)
        *(float4*)(xhf + (IN_DIM + j) * XST + boff + 4 * kt) =
            make_float4(hv[0], hv[1], hv[2], hv[3]);
    }

    // ---- classifier reduction over j ----
    __syncthreads();
    #pragma unroll
    for (int i = 0; i < 4; i++)
        shclf[(boff + 4 * kt + i) * 65 + j] = clf[i];
    __syncthreads();
    if (tid < BTILE) {
        float s = b_clf[0];
        #pragma unroll 8
        for (int jj = 0; jj < H_DIM; jj++) s += shclf[tid * 65 + jj];
        out[base + tid] = s;
    }
}

extern "C" void kernel_launch(void* const* d_in, const int* in_sizes, int n_in,
                              void* d_out, int out_size)
{
    const float* x     = (const float*)d_in[0];
    const float* w_ih  = (const float*)d_in[1];
    const float* w_hh  = (const float*)d_in[2];
    const float* b_ih  = (const float*)d_in[3];
    const float* b_hh  = (const float*)d_in[4];
    const float* w_clf = (const float*)d_in[5];
    const float* b_clf = (const float*)d_in[6];
    float* out = (float*)d_out;

    const int B = in_sizes[0] / TIN;   // 4096
    const int smem_bytes = SMEM_FLOATS * sizeof(float);

    cudaFuncSetAttribute(lstm_fused_kernel,
                         cudaFuncAttributeMaxDynamicSharedMemorySize, smem_bytes);
    lstm_fused_kernel<<<B / BTILE, NTHR, smem_bytes>>>(
        x, w_ih, w_hh, b_ih, b_hh, w_clf, b_clf, out);
}